// round 7
// baseline (speedup 1.0000x reference)
#include <cuda_runtime.h>
#include <stdint.h>

// Volume rendering: M rays x N=128 samples.
// Persistent grid-stride warps, one ray per warp per iteration, 4 samples/lane.
// Software prefetch: next ray's loads issued before current ray's compute,
// keeping loads in flight through the shuffle/exp phase.
// inputs: density [M*128] f32, feature [M*128*3] f32, depth [M*128] f32
// output: [M*4] f32 = (r, g, b, depth)

#define NSAMP 128

struct RayData {
    float4 sg, dp, f0, f1, f2;
};

__device__ __forceinline__ void load_ray(RayData& rd,
                                         const float* __restrict__ density,
                                         const float* __restrict__ feature,
                                         const float* __restrict__ depth,
                                         long ray, int lane)
{
    const long base = ray * NSAMP + lane * 4;
    rd.sg = __ldcs(reinterpret_cast<const float4*>(density + base));
    rd.dp = __ldcs(reinterpret_cast<const float4*>(depth + base));
    const float4* fptr = reinterpret_cast<const float4*>(feature + ray * NSAMP * 3 + lane * 12);
    rd.f0 = __ldcs(fptr + 0);
    rd.f1 = __ldcs(fptr + 1);
    rd.f2 = __ldcs(fptr + 2);
}

__device__ __forceinline__ void process_ray(const RayData& rd,
                                            float* __restrict__ out,
                                            long ray, int lane)
{
    const unsigned FULL = 0xFFFFFFFFu;
    const float4 sg = rd.sg, dp = rd.dp, f0 = rd.f0, f1 = rd.f1, f2 = rd.f2;

    // deltas: depth[j+1]-depth[j], terminal 1e10
    float next_dx = __shfl_down_sync(FULL, dp.x, 1);
    float dl0 = dp.y - dp.x;
    float dl1 = dp.z - dp.y;
    float dl2 = dp.w - dp.z;
    float dl3 = (lane == 31) ? 1e10f : (next_dx - dp.w);

    // tau = sigma * delta; cap terminal tau at 87 (exp(-87)~=0, identical
    // result) so the scan stays O(100) and a = s - p3 doesn't cancel.
    float t0 = sg.x * dl0;
    float t1 = sg.y * dl1;
    float t2 = sg.z * dl2;
    float t3 = fminf(sg.w * dl3, 87.0f);

    // local inclusive prefix
    float p0 = t0;
    float p1 = p0 + t1;
    float p2 = p1 + t2;
    float p3 = p2 + t3;

    // warp inclusive scan of lane sums
    float s = p3;
    #pragma unroll
    for (int off = 1; off < 32; off <<= 1) {
        float v = __shfl_up_sync(FULL, s, off);
        if (lane >= off) s += v;
    }
    const float a = s - p3;  // exclusive prefix for this lane's first sample

    // transmittance at boundaries
    float e0 = __expf(-a);
    float e1 = __expf(-(a + p0));
    float e2 = __expf(-(a + p1));
    float e3 = __expf(-(a + p2));
    float e4 = __expf(-(a + p3));

    // telescoping weights
    float w0 = e0 - e1;
    float w1 = e1 - e2;
    float w2 = e2 - e3;
    float w3 = e3 - e4;

    // accumulate rgb + depth
    float r = w0 * f0.x + w1 * f0.w + w2 * f1.z + w3 * f2.y;
    float g = w0 * f0.y + w1 * f1.x + w2 * f1.w + w3 * f2.z;
    float b = w0 * f0.z + w1 * f1.y + w2 * f2.x + w3 * f2.w;
    float d = w0 * dp.x + w1 * dp.y + w2 * dp.z + w3 * dp.w;

    // quad-reduce 4 components (8 shuffles), component-select, 3 butterflies
    #pragma unroll
    for (int off = 1; off <= 2; off <<= 1) {
        r += __shfl_xor_sync(FULL, r, off);
        g += __shfl_xor_sync(FULL, g, off);
        b += __shfl_xor_sync(FULL, b, off);
        d += __shfl_xor_sync(FULL, d, off);
    }
    const int c = lane & 3;
    float v = (c == 0) ? r : (c == 1) ? g : (c == 2) ? b : d;
    #pragma unroll
    for (int off = 4; off < 32; off <<= 1) {
        v += __shfl_xor_sync(FULL, v, off);
    }

    if (lane < 4) {
        out[ray * 4 + lane] = v;
    }
}

__global__ void __launch_bounds__(256) volren_kernel(
    const float* __restrict__ density,
    const float* __restrict__ feature,
    const float* __restrict__ depth,
    float* __restrict__ out,
    int M, int total_warps)
{
    const int lane = threadIdx.x & 31;
    const int wgid = blockIdx.x * (blockDim.x >> 5) + (threadIdx.x >> 5);

    long ray = wgid;
    if (ray >= M) return;

    RayData cur;
    load_ray(cur, density, feature, depth, ray, lane);

    for (; ray < M; ray += total_warps) {
        const long nray = ray + total_warps;
        RayData nxt;
        if (nray < M) {
            load_ray(nxt, density, feature, depth, nray, lane);
        }
        process_ray(cur, out, ray, lane);
        cur = nxt;
    }
}

extern "C" void kernel_launch(void* const* d_in, const int* in_sizes, int n_in,
                              void* d_out, int out_size) {
    const float* density = (const float*)d_in[0];
    const float* feature = (const float*)d_in[1];
    const float* depth   = (const float*)d_in[2];
    float* out = (float*)d_out;

    const int M = in_sizes[0] / NSAMP;  // 65536
    const int SMS = 148;
    const int blocks = SMS * 8;         // one persistent wave
    const int threads = 256;            // 8 warps/block
    const int total_warps = blocks * (threads / 32);
    volren_kernel<<<blocks, threads>>>(density, feature, depth, out, M, total_warps);
}